// round 8
// baseline (speedup 1.0000x reference)
#include <cuda_runtime.h>
#include <cuda_fp16.h>
#include <cstdint>

// ============================================================
// Typed relational GCN, sm_103 baseline PTX (no tcgen05 allowed).
//   out = sum_k (adj==k) @ (V@w_k) + bias,  N=8192, F=256, fp32.
//
// R8: R4 tiling (warp M16 x N128, best measured) + PRMT masks,
// but B fragments read DIRECTLY via LDG.128 from L2-resident
// global scratch. No shared memory, no cp.async, no barriers:
// warps run fully decoupled; L1 serves repeat readers.
// ============================================================

#define NROWS 8192
#define FEAT  256
#define NCHUNKS 128                           // K chunks of 64

// B scratch, fragment-major fp16:
// [type(3)][ntile(32)][kchunk(128)][half(2)][lane(32)][16B] = 12.58 MB
__device__ __align__(256) uint8_t g_B[3u * 32u * 128u * 2u * 32u * 16u];

// byte strides in g_B
#define BS_HALF   512u
#define BS_CHUNK  1024u
#define BS_NTILE  131072u
#define BS_TYPE   4194304u

// ---------------- helpers ---------------------------------------------------

__device__ __forceinline__ uint32_t prmt(uint32_t a, uint32_t b, uint32_t sel) {
    uint32_t r;
    asm("prmt.b32 %0, %1, %2, %3;" : "=r"(r) : "r"(a), "r"(b), "r"(sel));
    return r;
}

// pack low bytes of 4 int32 (values 0..3) into one 4-byte word
__device__ __forceinline__ uint32_t pack4(int a, int b, int c, int d) {
    uint32_t x, y, r;
    asm("prmt.b32 %0, %1, %2, 0x40;"   : "=r"(x) : "r"(a), "r"(b));
    asm("prmt.b32 %0, %1, %2, 0x40;"   : "=r"(y) : "r"(c), "r"(d));
    asm("prmt.b32 %0, %1, %2, 0x5410;" : "=r"(r) : "r"(x), "r"(y));
    return r;
}

__device__ __forceinline__ void mma_f16(float* c,
                                        uint32_t a0, uint32_t a1, uint32_t a2, uint32_t a3,
                                        uint32_t b0, uint32_t b1) {
    asm volatile(
        "mma.sync.aligned.m16n8k16.row.col.f32.f16.f16.f32 "
        "{%0,%1,%2,%3}, {%4,%5,%6,%7}, {%8,%9}, {%0,%1,%2,%3};"
        : "+f"(c[0]), "+f"(c[1]), "+f"(c[2]), "+f"(c[3])
        : "r"(a0), "r"(a1), "r"(a2), "r"(a3), "r"(b0), "r"(b1));
}

__device__ __forceinline__ uint4 ldg128(const uint8_t* p) {
    uint4 v;
    asm volatile("ld.global.nc.v4.u32 {%0,%1,%2,%3}, [%4];"
                 : "=r"(v.x), "=r"(v.y), "=r"(v.z), "=r"(v.w) : "l"(p));
    return v;
}

// ---------------- Stage 1: H_k = V @ w_k -> fp16 fragment-major -------------
// grid (128 j-tiles, 4 n-tiles, 3 types), block (16,16). FFMA-roofline bound.

__global__ void stage1_kernel(const float* __restrict__ V,
                              const float* __restrict__ w1,
                              const float* __restrict__ w2,
                              const float* __restrict__ w3) {
    const int j0 = blockIdx.x * 64;
    const int n0 = blockIdx.y * 64;
    const int type = blockIdx.z;
    const float* w = (type == 0) ? w1 : (type == 1) ? w2 : w3;

    __shared__ float Vs[16][68];
    __shared__ float Ws[16][68];
    __shared__ float Ts[64][65];           // [n][j]

    const int tx = threadIdx.x, ty = threadIdx.y;
    const int t = ty * 16 + tx;

    float acc[4][4];
#pragma unroll
    for (int i = 0; i < 4; i++)
#pragma unroll
        for (int j = 0; j < 4; j++) acc[i][j] = 0.f;

    const int vrow = t >> 2, vci = (t & 3) * 4;
    const int wc = t >> 4, wn = (t & 15) * 4;

    for (int ks = 0; ks < 16; ks++) {
        float4 v = *(const float4*)&V[(size_t)(j0 + vrow) * 256 + ks * 16 + vci];
        Vs[vci + 0][vrow] = v.x; Vs[vci + 1][vrow] = v.y;
        Vs[vci + 2][vrow] = v.z; Vs[vci + 3][vrow] = v.w;
        *(float4*)&Ws[wc][wn] = *(const float4*)&w[(size_t)(ks * 16 + wc) * 256 + n0 + wn];
        __syncthreads();
#pragma unroll
        for (int c = 0; c < 16; c++) {
            float4 rv = *(const float4*)&Vs[c][ty * 4];
            float4 rw = *(const float4*)&Ws[c][tx * 4];
            float a[4] = {rv.x, rv.y, rv.z, rv.w};
            float b[4] = {rw.x, rw.y, rw.z, rw.w};
#pragma unroll
            for (int i = 0; i < 4; i++)
#pragma unroll
                for (int j = 0; j < 4; j++) acc[i][j] += a[i] * b[j];
        }
        __syncthreads();
    }
#pragma unroll
    for (int i = 0; i < 4; i++)
#pragma unroll
        for (int j = 0; j < 4; j++) Ts[tx * 4 + j][ty * 4 + i] = acc[i][j];
    __syncthreads();

    // fragment-major fp16 write.
    const int nl = t >> 2;
    const int s = t & 3;
    const int jb = s * 16;
    const int n = n0 + nl;
    const int nt = n >> 3;
    const int kc = blockIdx.x;

#pragma unroll
    for (int c = 0; c < 4; c++) {
        __half2 p01 = __floats2half2_rn(Ts[nl][jb + 2 * c], Ts[nl][jb + 2 * c + 1]);
        __half2 p89 = __floats2half2_rn(Ts[nl][jb + 2 * c + 8], Ts[nl][jb + 2 * c + 9]);
        uint2 val = make_uint2(*reinterpret_cast<uint32_t*>(&p01),
                               *reinterpret_cast<uint32_t*>(&p89));
        const int lane = 4 * (n & 7) + c;
        size_t off = (size_t)type * BS_TYPE + (size_t)nt * BS_NTILE + (size_t)kc * BS_CHUNK
                   + (size_t)(s >> 1) * BS_HALF + (size_t)lane * 16 + (size_t)(s & 1) * 8;
        *(uint2*)&g_B[off] = val;
    }
}

// ---------------- Stage 2: mask-GEMM, warp M16 x N128, no smem --------------
// grid 128: bid -> (m_tile = bid>>1 of 128 rows, n_half = bid&1 of 128 feats).
// 256 threads, 8 warps, zero shared memory, zero barriers.

__global__ void __launch_bounds__(256, 1)
stage2_kernel(const int* __restrict__ adj,
              const float* __restrict__ bias,
              float* __restrict__ out) {
    const int tid = threadIdx.x;
    const int wid = tid >> 5, l = tid & 31;
    const int m_tile = blockIdx.x >> 1;
    const int n_half = blockIdx.x & 1;
    const int i0 = m_tile * 128;
    const int n0 = n_half * 128;
    const int li = l & 3;

    const int rowA = i0 + wid * 16 + (l >> 2);
    const int2* aA = (const int2*)(adj + (size_t)rowA * NROWS);
    const int2* aB = (const int2*)(adj + (size_t)(rowA + 8) * NROWS);

    // lane-resolved B base for this warp's n_half
    const uint8_t* blane = g_B + (size_t)(n_half * 16) * BS_NTILE + (size_t)l * 16;

    float acc[16][4];
#pragma unroll
    for (int nt = 0; nt < 16; nt++)
#pragma unroll
        for (int r = 0; r < 4; r++) acc[nt][r] = 0.f;

    // preload adj chunk 0
    int2 v[2][4][2];
#pragma unroll
    for (int s = 0; s < 4; s++) {
        v[0][s][0] = aA[8 * s + li];
        v[0][s][1] = aA[8 * s + li + 4];
        v[1][s][0] = aB[8 * s + li];
        v[1][s][1] = aB[8 * s + li + 4];
    }

    for (int c = 0; c < NCHUNKS; c++) {
        // pack current adj bytes: pk[ab][s] = [k0, k1, k8, k9], k0 = 16s+2li
        uint32_t pk[2][4];
#pragma unroll
        for (int ab = 0; ab < 2; ab++)
#pragma unroll
            for (int s = 0; s < 4; s++)
                pk[ab][s] = pack4(v[ab][s][0].x, v[ab][s][0].y,
                                  v[ab][s][1].x, v[ab][s][1].y);

        // prefetch adj for next chunk (lands during this chunk's MMAs)
        if (c + 1 < NCHUNKS) {
            const int base = (c + 1) * 32;
#pragma unroll
            for (int s = 0; s < 4; s++) {
                v[0][s][0] = aA[base + 8 * s + li];
                v[0][s][1] = aA[base + 8 * s + li + 4];
                v[1][s][0] = aB[base + 8 * s + li];
                v[1][s][1] = aB[base + 8 * s + li + 4];
            }
        }

        const uint8_t* bc = blane + (size_t)c * BS_CHUNK;
#pragma unroll
        for (int t = 0; t < 3; t++) {
            // PRMT one-hot fp16 A fragments for all 4 ksteps
            const uint32_t cmp = 0x01010101u * (t + 1);
            uint32_t am[4][4];
#pragma unroll
            for (int s = 0; s < 4; s++) {
                uint32_t eA = __vcmpeq4(pk[0][s], cmp) & 0x3C3C3C3Cu;
                uint32_t eB = __vcmpeq4(pk[1][s], cmp) & 0x3C3C3C3Cu;
                am[s][0] = prmt(eA, 0u, 0x1404u);   // rowA, {k0,k1}
                am[s][1] = prmt(eB, 0u, 0x1404u);   // rowB, {k0,k1}
                am[s][2] = prmt(eA, 0u, 0x3424u);   // rowA, {k8,k9}
                am[s][3] = prmt(eB, 0u, 0x3424u);   // rowB, {k8,k9}
            }
            const uint8_t* bt = bc + (size_t)t * BS_TYPE;
            // nt groups of 4: batch 8 independent LDG.128, then 16 MMAs
            // issued s-outer so consecutive MMAs hit different accumulators
#pragma unroll
            for (int g = 0; g < 4; g++) {
                uint4 ub[4][2];
#pragma unroll
                for (int n4 = 0; n4 < 4; n4++) {
                    const uint8_t* p = bt + (size_t)(g * 4 + n4) * BS_NTILE;
                    ub[n4][0] = ldg128(p);
                    ub[n4][1] = ldg128(p + BS_HALF);
                }
#pragma unroll
                for (int s = 0; s < 4; s++) {
#pragma unroll
                    for (int n4 = 0; n4 < 4; n4++) {
                        const uint32_t b0 = (s & 1) ? ub[n4][s >> 1].z : ub[n4][s >> 1].x;
                        const uint32_t b1 = (s & 1) ? ub[n4][s >> 1].w : ub[n4][s >> 1].y;
                        mma_f16(acc[g * 4 + n4],
                                am[s][0], am[s][1], am[s][2], am[s][3], b0, b1);
                    }
                }
            }
        }
    }

    // epilogue: out = acc + bias
#pragma unroll
    for (int nt = 0; nt < 16; nt++) {
        int col = n0 + nt * 8 + 2 * (l & 3);
        float b0 = __ldg(&bias[col]);
        float b1 = __ldg(&bias[col + 1]);
        float2 w0 = make_float2(acc[nt][0] + b0, acc[nt][1] + b1);
        float2 w1 = make_float2(acc[nt][2] + b0, acc[nt][3] + b1);
        *(float2*)&out[(size_t)rowA * FEAT + col] = w0;
        *(float2*)&out[(size_t)(rowA + 8) * FEAT + col] = w1;
    }
}

// ---------------- launch ---------------------------------------------------

extern "C" void kernel_launch(void* const* d_in, const int* in_sizes, int n_in,
                              void* d_out, int out_size) {
    const float* V    = (const float*)d_in[0];
    const int*   adj  = (const int*)d_in[1];
    const float* w1   = (const float*)d_in[2];
    const float* w2   = (const float*)d_in[3];
    const float* w3   = (const float*)d_in[4];
    const float* bias = (const float*)d_in[5];
    float* out = (float*)d_out;

    stage1_kernel<<<dim3(128, 4, 3), dim3(16, 16)>>>(V, w1, w2, w3);
    stage2_kernel<<<128, 256>>>(adj, bias, out);
}